// round 10
// baseline (speedup 1.0000x reference)
#include <cuda_runtime.h>
#include <cuda_bf16.h>
#include <math.h>

// H = [[1.2, c],[c, 0.01]], c = cos(theta)
// inv = 1/(1.2*0.01 - c^2) * [[0.01, -c],[-c, 1.2]]
//
// Numerics (verified, rel_err 1.92e-5): bulk = __cosf + rcp.approx;
// near-singular elements (|det| < 1e-5) redo with correctly-rounded fp32 cos
// (via fp64) + correctly-rounded divide — they own the reference L2 norm.
//
// Perf history:
//   R3: 1 elem/thread, __fdiv_rn          -> 36.2us
//   R4: float4 load + store burst + stcs  -> 39.4us REGRESSED (store burst bad)
//   R7: 1 elem/thread, rcp.approx         -> 35.3us, DRAM 43%  (MLP=1 bound)
//   R8: 4 elem/thread, front-batched LDGs -> 29.9us, DRAM 54.8% (MLP=4)
//   R9: 8 elem/thread, front-batched LDGs (MLP_p1=8), stores still
//       interleaved one STG.128 per element. Same lever, turned further.

__device__ __forceinline__ float rcp_approx(float x) {
    float r;
    asm("rcp.approx.f32 %0, %1;" : "=f"(r) : "f"(x));
    return r;
}

__device__ __forceinline__ float4 invert_one(float t)
{
    const float ad = 1.2f * 0.01f;

    float c   = __cosf(t);
    float det = __fsub_rn(ad, __fmul_rn(c, c));
    float r   = rcp_approx(det);

    if (fabsf(det) < 1e-5f) {                 // ~0.005% of elements
        c   = (float)cos((double)t);
        det = __fsub_rn(ad, __fmul_rn(c, c));
        r   = __fdiv_rn(1.0f, det);
    }

    float4 v;
    v.x = __fmul_rn(0.01f, r);
    v.y = __fmul_rn(-c,    r);
    v.z = v.y;
    v.w = __fmul_rn(1.2f,  r);
    return v;
}

__global__ __launch_bounds__(256) void inv2x2_kernel_v9(
    const float* __restrict__ theta,
    float4* __restrict__ out,
    int n)
{
    const int T = 256;                          // blockDim.x
    const int E = 8;                            // elements per thread
    int base = blockIdx.x * (T * E) + threadIdx.x;

    if (base + (E - 1) * T < n) {
        // Front-batched independent loads: 8 coalesced 128B warp LDGs in
        // flight before any compute (MLP_p1 = 8).
        float t0 = __ldg(&theta[base]);
        float t1 = __ldg(&theta[base +     T]);
        float t2 = __ldg(&theta[base + 2 * T]);
        float t3 = __ldg(&theta[base + 3 * T]);
        float t4 = __ldg(&theta[base + 4 * T]);
        float t5 = __ldg(&theta[base + 5 * T]);
        float t6 = __ldg(&theta[base + 6 * T]);
        float t7 = __ldg(&theta[base + 7 * T]);

        // Compute + store interleaved; each store is a coalesced 512B/warp
        // STG.128 (proven shape — no bursting, no evict hints).
        out[base]         = invert_one(t0);
        out[base +     T] = invert_one(t1);
        out[base + 2 * T] = invert_one(t2);
        out[base + 3 * T] = invert_one(t3);
        out[base + 4 * T] = invert_one(t4);
        out[base + 5 * T] = invert_one(t5);
        out[base + 6 * T] = invert_one(t6);
        out[base + 7 * T] = invert_one(t7);
    } else {
        // Tail (unused for n = 8388608, divisible by 2048).
        for (int k = 0; k < E; k++) {
            int i = base + k * T;
            if (i < n) out[i] = invert_one(__ldg(&theta[i]));
        }
    }
}

extern "C" void kernel_launch(void* const* d_in, const int* in_sizes, int n_in,
                              void* d_out, int out_size) {
    const float* theta = (const float*)d_in[0];
    float4* out = (float4*)d_out;
    int n = in_sizes[0];                        // 8388608

    const int threads = 256;
    int elems_per_block = threads * 8;          // 2048
    int blocks = (n + elems_per_block - 1) / elems_per_block;   // 4096
    inv2x2_kernel_v9<<<blocks, threads>>>(theta, out, n);
}